// round 2
// baseline (speedup 1.0000x reference)
#include <cuda_runtime.h>
#include <cuda_bf16.h>
#include <math.h>
#include <stdint.h>

#define T 1024
#define H 1024
#define NH 8
#define NKV 4
#define HD 128
#define NE 32
#define MI 512
#define SI 1024

// ---------------- scratch ----------------
__device__ float g_h1[T*H];
__device__ float g_qkv[T*2048];          // q | k | v fused
__device__ float g_attn[T*H];
__device__ float g_ao[T*H];
__device__ float g_h2[T*H];
__device__ float g_x[T*H];
__device__ float g_logits[T*NE];
__device__ float g_topkw[T*4];
__device__ int   g_cnt[NE];
__device__ int   g_list[NE*T];
__device__ float g_egu[(size_t)T*4*1024];  // eg | eu fused per row
__device__ float g_act[(size_t)T*4*512];
__device__ float g_ed[(size_t)T*4*H];
__device__ float g_sgu[T*2048];            // sg | su fused
__device__ float g_act2[T*SI];
__device__ float g_sh[T*H];

// ---------------- small helpers ----------------
__device__ __forceinline__ uint32_t smem_u32(const void* p) {
    return (uint32_t)__cvta_generic_to_shared(p);
}
__device__ __forceinline__ void ldmatrix_x4(uint32_t* r, uint32_t a) {
    asm volatile("ldmatrix.sync.aligned.m8n8.x4.shared.b16 {%0,%1,%2,%3}, [%4];"
        : "=r"(r[0]), "=r"(r[1]), "=r"(r[2]), "=r"(r[3]) : "r"(a));
}
__device__ __forceinline__ void ldmatrix_x2(uint32_t* r, uint32_t a) {
    asm volatile("ldmatrix.sync.aligned.m8n8.x2.shared.b16 {%0,%1}, [%2];"
        : "=r"(r[0]), "=r"(r[1]) : "r"(a));
}
__device__ __forceinline__ void ldmatrix_x2_trans(uint32_t* r, uint32_t a) {
    asm volatile("ldmatrix.sync.aligned.m8n8.x2.trans.shared.b16 {%0,%1}, [%2];"
        : "=r"(r[0]), "=r"(r[1]) : "r"(a));
}
__device__ __forceinline__ void mma16816(float* c, const uint32_t* a, const uint32_t* b) {
    asm volatile("mma.sync.aligned.m16n8k16.row.col.f32.bf16.bf16.f32 "
        "{%0,%1,%2,%3},{%4,%5,%6,%7},{%8,%9},{%0,%1,%2,%3};"
        : "+f"(c[0]), "+f"(c[1]), "+f"(c[2]), "+f"(c[3])
        : "r"(a[0]), "r"(a[1]), "r"(a[2]), "r"(a[3]), "r"(b[0]), "r"(b[1]));
}
// split fp32 -> (hi, lo) bf16 planes; x = hi + lo up to ~2^-18 rel
__device__ __forceinline__ void store_split(__nv_bfloat16* hp, __nv_bfloat16* lp, float4 f) {
    __nv_bfloat16 h0 = __float2bfloat16(f.x), h1 = __float2bfloat16(f.y);
    __nv_bfloat16 h2 = __float2bfloat16(f.z), h3 = __float2bfloat16(f.w);
    float r0 = f.x - __bfloat162float(h0), r1 = f.y - __bfloat162float(h1);
    float r2 = f.z - __bfloat162float(h2), r3 = f.w - __bfloat162float(h3);
    *(__nv_bfloat162*)(hp)     = __halves2bfloat162(h0, h1);
    *(__nv_bfloat162*)(hp + 2) = __halves2bfloat162(h2, h3);
    *(__nv_bfloat162*)(lp)     = __halves2bfloat162(__float2bfloat16(r0), __float2bfloat16(r1));
    *(__nv_bfloat162*)(lp + 2) = __halves2bfloat162(__float2bfloat16(r2), __float2bfloat16(r3));
}

// ---------------- split-bf16 tensor-core GEMM ----------------
// C[M,N] = A[M,K] @ op(B), fp32 in/out, bf16-split (3 HMMA products) internally.
// BT=true : B rows are output features: element B[n][k] (NT)
// BT=false: element B[k][n] (NN)
// B can be split into up to 4 n-segments of 512 cols each (weight fusion).
struct BSegs {
    const float* seg[4];
    int base[4];
    int ldb;
    size_t estride;   // per-expert element stride (GATHER only)
};

template <bool BT, bool GATHER>
__global__ __launch_bounds__(256)
void gemm_bf16(const float* __restrict__ A, int lda, BSegs B,
               float* __restrict__ C, int ldc, int M, int N, int K,
               const int* __restrict__ cnt, const int* __restrict__ list, int shift) {
    const int tid = threadIdx.x;
    const int m0 = blockIdx.y * 128;
    const int n0 = blockIdx.x * 128;
    const int e = GATHER ? blockIdx.z : 0;

    __shared__ int rows_s[128];
    if (GATHER) {
        int me = cnt[e];
        if (m0 >= me) return;
        if (tid < 128) rows_s[tid] = (m0 + tid < me) ? list[e * T + m0 + tid] : -1;
    }

    // SMEM tiles: A[128][32] and B as either [128 n][32 k] (NT) or [32 k][128 n] (NN)
    __shared__ __align__(16) __nv_bfloat16 AsH[128 * 40];
    __shared__ __align__(16) __nv_bfloat16 AsL[128 * 40];
    __shared__ __align__(16) __nv_bfloat16 BsH[BT ? 128 * 40 : 32 * 136];
    __shared__ __align__(16) __nv_bfloat16 BsL[BT ? 128 * 40 : 32 * 136];

    const int lane = tid & 31, wid = tid >> 5;
    const int wm = wid >> 2, wn = wid & 3;   // warp grid 2 (m) x 4 (n)

    float acc[4][4][4] = {};
    __syncthreads();   // rows_s visible

    for (int k0 = 0; k0 < K; k0 += 32) {
        // ---- A tile 128x32 ----
        {
            int r = tid >> 3;
            int c4 = (tid & 7) * 4;
#pragma unroll
            for (int it = 0; it < 4; it++, r += 32) {
                float4 f;
                if (GATHER) {
                    int j = rows_s[r];
                    if (j >= 0) f = *(const float4*)(A + (size_t)(j >> shift) * lda + k0 + c4);
                    else f = make_float4(0.f, 0.f, 0.f, 0.f);
                } else {
                    f = *(const float4*)(A + (size_t)(m0 + r) * lda + k0 + c4);
                }
                store_split(&AsH[r * 40 + c4], &AsL[r * 40 + c4], f);
            }
        }
        // ---- B tile ----
        if (BT) {
            int r = tid >> 3;
            int c4 = (tid & 7) * 4;
#pragma unroll
            for (int it = 0; it < 4; it++, r += 32) {
                int gn = n0 + r;
                int sgi = gn >> 9;
                const float* bp = B.seg[sgi] + (size_t)e * B.estride +
                                  (size_t)(gn - B.base[sgi]) * B.ldb + k0 + c4;
                float4 f = *(const float4*)bp;
                store_split(&BsH[r * 40 + c4], &BsL[r * 40 + c4], f);
            }
        } else {
            int kr = tid >> 5;
            int c4 = (tid & 31) * 4;
#pragma unroll
            for (int it = 0; it < 4; it++, kr += 8) {
                int gn = n0 + c4;
                int sgi = gn >> 9;
                const float* bp = B.seg[sgi] + (size_t)e * B.estride +
                                  (size_t)(k0 + kr) * B.ldb + (gn - B.base[sgi]);
                float4 f = *(const float4*)bp;
                store_split(&BsH[kr * 136 + c4], &BsL[kr * 136 + c4], f);
            }
        }
        __syncthreads();

#pragma unroll
        for (int s = 0; s < 2; s++) {
            uint32_t ah[4][4], al[4][4];
#pragma unroll
            for (int i = 0; i < 4; i++) {
                int row = wm * 64 + i * 16 + ((lane >> 3) & 1) * 8 + (lane & 7);
                int col = s * 16 + (lane >> 4) * 8;
                ldmatrix_x4(ah[i], smem_u32(&AsH[row * 40 + col]));
                ldmatrix_x4(al[i], smem_u32(&AsL[row * 40 + col]));
            }
#pragma unroll
            for (int j = 0; j < 4; j++) {
                uint32_t bh[2], bl[2];
                int nb = wn * 32 + j * 8;
                int l = lane & 15;
                if (BT) {
                    int row = nb + (l & 7);
                    int col = s * 16 + ((l >> 3) & 1) * 8;
                    ldmatrix_x2(bh, smem_u32(&BsH[row * 40 + col]));
                    ldmatrix_x2(bl, smem_u32(&BsL[row * 40 + col]));
                } else {
                    int kk = s * 16 + ((l >> 3) & 1) * 8 + (l & 7);
                    ldmatrix_x2_trans(bh, smem_u32(&BsH[kk * 136 + nb]));
                    ldmatrix_x2_trans(bl, smem_u32(&BsL[kk * 136 + nb]));
                }
#pragma unroll
                for (int i = 0; i < 4; i++) {
                    mma16816(acc[i][j], ah[i], bh);
                    mma16816(acc[i][j], al[i], bh);
                    mma16816(acc[i][j], ah[i], bl);
                }
            }
        }
        __syncthreads();
    }

    // ---- epilogue ----
#pragma unroll
    for (int i = 0; i < 4; i++) {
        int lr = wm * 64 + i * 16 + (lane >> 2);
#pragma unroll
        for (int j = 0; j < 4; j++) {
            int col = n0 + wn * 32 + j * 8 + (lane & 3) * 2;
            if (GATHER) {
                int j0 = rows_s[lr];
                if (j0 >= 0)
                    *(float2*)(C + (size_t)j0 * ldc + col) = make_float2(acc[i][j][0], acc[i][j][1]);
                int j1 = rows_s[lr + 8];
                if (j1 >= 0)
                    *(float2*)(C + (size_t)j1 * ldc + col) = make_float2(acc[i][j][2], acc[i][j][3]);
            } else {
                int gr = m0 + lr;
                *(float2*)(C + (size_t)gr * ldc + col) = make_float2(acc[i][j][0], acc[i][j][1]);
                *(float2*)(C + (size_t)(gr + 8) * ldc + col) = make_float2(acc[i][j][2], acc[i][j][3]);
            }
        }
    }
}

// ---------------- fp32 tiled GEMM (router only, N=32) ----------------
__global__ void gemm_f32_nt(const float* __restrict__ A, const float* __restrict__ B,
                            float* __restrict__ C, int M, int N, int K) {
    __shared__ float As[16][68];
    __shared__ float Bs[16][68];
    const int tid = threadIdx.x;
    const int m0 = blockIdx.y * 64, n0 = blockIdx.x * 64;
    const int tx = tid & 15, ty = tid >> 4;
    const int ar = tid >> 2, ac = (tid & 3) * 4;
    float acc[4][4] = {};
    for (int k0 = 0; k0 < K; k0 += 16) {
        {
            int gm = m0 + ar;
            float4 f = make_float4(0.f, 0.f, 0.f, 0.f);
            if (gm < M) f = *(const float4*)(A + (size_t)gm * K + k0 + ac);
            As[ac + 0][ar] = f.x; As[ac + 1][ar] = f.y;
            As[ac + 2][ar] = f.z; As[ac + 3][ar] = f.w;
        }
        {
            int gn = n0 + ar;
            float4 f = make_float4(0.f, 0.f, 0.f, 0.f);
            if (gn < N) f = *(const float4*)(B + (size_t)gn * K + k0 + ac);
            Bs[ac + 0][ar] = f.x; Bs[ac + 1][ar] = f.y;
            Bs[ac + 2][ar] = f.z; Bs[ac + 3][ar] = f.w;
        }
        __syncthreads();
#pragma unroll
        for (int kk = 0; kk < 16; kk++) {
            float a[4], b[4];
#pragma unroll
            for (int i = 0; i < 4; i++) a[i] = As[kk][ty * 4 + i];
#pragma unroll
            for (int j = 0; j < 4; j++) b[j] = Bs[kk][tx * 4 + j];
#pragma unroll
            for (int i = 0; i < 4; i++)
#pragma unroll
                for (int j = 0; j < 4; j++) acc[i][j] = fmaf(a[i], b[j], acc[i][j]);
        }
        __syncthreads();
    }
#pragma unroll
    for (int i = 0; i < 4; i++) {
        int gm = m0 + ty * 4 + i;
        if (gm >= M) continue;
#pragma unroll
        for (int j = 0; j < 4; j++) {
            int gn = n0 + tx * 4 + j;
            if (gn < N) C[(size_t)gm * N + gn] = acc[i][j];
        }
    }
}

// ---------------- elementwise / norms ----------------
__global__ void rmsnorm_kernel(const float* __restrict__ x, const float* __restrict__ w,
                               float* __restrict__ out) {
    int t = blockIdx.x;
    const float* xr = x + (size_t)t * H;
    float s = 0.f;
    for (int i = threadIdx.x; i < H; i += blockDim.x) { float v = xr[i]; s += v * v; }
    __shared__ float red[32];
    for (int o = 16; o; o >>= 1) s += __shfl_xor_sync(0xffffffffu, s, o);
    if ((threadIdx.x & 31) == 0) red[threadIdx.x >> 5] = s;
    __syncthreads();
    if (threadIdx.x < 32) {
        float v = (threadIdx.x < (blockDim.x >> 5)) ? red[threadIdx.x] : 0.f;
        for (int o = 16; o; o >>= 1) v += __shfl_xor_sync(0xffffffffu, v, o);
        if (threadIdx.x == 0) red[0] = v;
    }
    __syncthreads();
    float inv = rsqrtf(red[0] * (1.f / H) + 1e-6f);
    for (int i = threadIdx.x; i < H; i += blockDim.x)
        out[(size_t)t * H + i] = xr[i] * inv * w[i];
}

__global__ void add_kernel(const float* __restrict__ a, const float* __restrict__ b,
                           float* __restrict__ o, int n) {
    int i = blockIdx.x * blockDim.x + threadIdx.x;
    if (i < n) o[i] = a[i] + b[i];
}

// fused-layout silu: g at x[r*ldx+c], u at x[r*ldx+w+c], out o[r*w+c]
__global__ void silu_pair_kernel(const float* __restrict__ x, float* __restrict__ o,
                                 int total, int w, int ldx) {
    int idx = blockIdx.x * blockDim.x + threadIdx.x;
    if (idx >= total) return;
    int r = idx / w, c = idx - r * w;
    float g = x[(size_t)r * ldx + c];
    float u = x[(size_t)r * ldx + w + c];
    o[idx] = g / (1.f + __expf(-g)) * u;
}

__global__ void zero_cnt_kernel(int* cnt) {
    if (threadIdx.x < NE) cnt[threadIdx.x] = 0;
}

// ---------------- RoPE (on fused qkv buffer, row stride 2048) ----------------
__global__ void rope_kernel(float* __restrict__ qkv, const int* __restrict__ pos) {
    int t = blockIdx.x;
    int i = threadIdx.x;          // 0..63
    int hh = threadIdx.y;         // 0..11 : 8 q-heads then 4 kv-heads
    float p = (float)pos[t];
    float inv = exp2f(-(float)i * (13.287712379549449f / 64.f));
    float fr = p * inv;
    float sv, cv;
    sincosf(fr, &sv, &cv);
    float* base = (hh < 8) ? (qkv + (size_t)t * 2048 + hh * HD)
                           : (qkv + (size_t)t * 2048 + 1024 + (hh - 8) * HD);
    float x1 = base[i], x2 = base[i + 64];
    base[i]      = x1 * cv - x2 * sv;
    base[i + 64] = x2 * cv + x1 * sv;
}

// ---------------- causal flash attention (fp32) ----------------
__global__ void attn_kernel(const float* __restrict__ qkv, float* __restrict__ out) {
    const int h = blockIdx.x;
    const int qt = gridDim.y - 1 - blockIdx.y;
    const int kvh = h >> 1;
    const int warp = threadIdx.x >> 5, lane = threadIdx.x & 31;
    __shared__ float Ks[32][HD];
    __shared__ float Vs[32][HD];
    const int q0 = qt * 32 + warp * 4;
    float qr[4][4];
#pragma unroll
    for (int i = 0; i < 4; i++) {
        float4 f = *(const float4*)(qkv + (size_t)(q0 + i) * 2048 + h * HD + lane * 4);
        qr[i][0] = f.x; qr[i][1] = f.y; qr[i][2] = f.z; qr[i][3] = f.w;
    }
    float acc[4][4] = {};
    float mx[4] = {-1e30f, -1e30f, -1e30f, -1e30f};
    float ls[4] = {0.f, 0.f, 0.f, 0.f};
    const float scale = 0.088388347648318447f;
    for (int kt = 0; kt <= qt; kt++) {
        __syncthreads();
        for (int r = warp; r < 32; r += 8) {
            int kr = kt * 32 + r;
            *(float4*)&Ks[r][lane * 4] =
                *(const float4*)(qkv + (size_t)kr * 2048 + 1024 + kvh * HD + lane * 4);
            *(float4*)&Vs[r][lane * 4] =
                *(const float4*)(qkv + (size_t)kr * 2048 + 1536 + kvh * HD + lane * 4);
        }
        __syncthreads();
        const bool diag = (kt == qt);
        for (int j = 0; j < 32; j++) {
            const int kg = kt * 32 + j;
            float kv0 = Ks[j][lane * 4 + 0], kv1 = Ks[j][lane * 4 + 1];
            float kv2 = Ks[j][lane * 4 + 2], kv3 = Ks[j][lane * 4 + 3];
            float4 vv = *(const float4*)&Vs[j][lane * 4];
#pragma unroll
            for (int i = 0; i < 4; i++) {
                if (diag && kg > q0 + i) continue;
                float p = qr[i][0] * kv0 + qr[i][1] * kv1 + qr[i][2] * kv2 + qr[i][3] * kv3;
                p += __shfl_xor_sync(0xffffffffu, p, 16);
                p += __shfl_xor_sync(0xffffffffu, p, 8);
                p += __shfl_xor_sync(0xffffffffu, p, 4);
                p += __shfl_xor_sync(0xffffffffu, p, 2);
                p += __shfl_xor_sync(0xffffffffu, p, 1);
                float s = p * scale;
                if (s > mx[i]) {
                    float c = __expf(mx[i] - s);
                    ls[i] = ls[i] * c + 1.f;
                    acc[i][0] = acc[i][0] * c + vv.x;
                    acc[i][1] = acc[i][1] * c + vv.y;
                    acc[i][2] = acc[i][2] * c + vv.z;
                    acc[i][3] = acc[i][3] * c + vv.w;
                    mx[i] = s;
                } else {
                    float e = __expf(s - mx[i]);
                    ls[i] += e;
                    acc[i][0] += e * vv.x;
                    acc[i][1] += e * vv.y;
                    acc[i][2] += e * vv.z;
                    acc[i][3] += e * vv.w;
                }
            }
        }
    }
#pragma unroll
    for (int i = 0; i < 4; i++) {
        float inv = 1.f / ls[i];
        float4 o;
        o.x = acc[i][0] * inv; o.y = acc[i][1] * inv;
        o.z = acc[i][2] * inv; o.w = acc[i][3] * inv;
        *(float4*)(out + (size_t)(q0 + i) * H + h * HD + lane * 4) = o;
    }
}

// ---------------- router ----------------
__global__ void router_kernel(const float* __restrict__ logits, const float* __restrict__ bias,
                              float* __restrict__ topkw, int* __restrict__ cnt,
                              int* __restrict__ list) {
    int t = blockIdx.x * blockDim.x + threadIdx.x;
    if (t >= T) return;
    float sc[NE], sfc[NE];
#pragma unroll
    for (int e = 0; e < NE; e++) {
        float l = logits[t * NE + e];
        float s = 1.f / (1.f + __expf(-l));
        sc[e] = s; sfc[e] = s + bias[e];
    }
    float gs[8];
#pragma unroll
    for (int g = 0; g < 8; g++) {
        float v[4] = {sfc[g*4+0], sfc[g*4+1], sfc[g*4+2], sfc[g*4+3]};
        float sum = v[0] + v[1] + v[2] + v[3];
        int mi = 0;
        for (int i = 1; i < 4; i++) if (v[i] < v[mi]) mi = i;
        float m2 = 1e30f;
        for (int i = 0; i < 4; i++) if (i != mi && v[i] < m2) m2 = v[i];
        gs[g] = sum - v[mi] - m2;
    }
    bool gsel[8] = {};
    for (int r = 0; r < 4; r++) {
        float best = -1e30f; int bi = 0;
        for (int g = 0; g < 8; g++) if (!gsel[g] && gs[g] > best) { best = gs[g]; bi = g; }
        gsel[bi] = true;
    }
    float masked[NE];
#pragma unroll
    for (int e = 0; e < NE; e++) masked[e] = gsel[e >> 2] ? sfc[e] : 0.f;
    int idxs[4]; float ws[4]; float wsum = 0.f;
    for (int r = 0; r < 4; r++) {
        float best = -1e30f; int bi = 0;
        for (int e = 0; e < NE; e++) if (masked[e] > best) { best = masked[e]; bi = e; }
        masked[bi] = -1e30f;
        idxs[r] = bi; ws[r] = sc[bi]; wsum += ws[r];
    }
    float inv = 2.5f / (wsum + 1e-20f);
    for (int r = 0; r < 4; r++) {
        topkw[t * 4 + r] = ws[r] * inv;
        int e = idxs[r];
        int pos = atomicAdd(&cnt[e], 1);
        list[e * T + pos] = t * 4 + r;
    }
}

// ---------------- final combine ----------------
__global__ void final_kernel(const float* __restrict__ h2, const float* __restrict__ sh,
                             const float* __restrict__ ed, const float* __restrict__ tw,
                             float* __restrict__ out) {
    int idx = blockIdx.x * blockDim.x + threadIdx.x;
    if (idx >= T * H) return;
    int t = idx >> 10;
    int hh = idx & 1023;
    float r = h2[idx] + sh[idx];
#pragma unroll
    for (int kk = 0; kk < 4; kk++)
        r += tw[t * 4 + kk] * ed[(size_t)(t * 4 + kk) * H + hh];
    out[idx] = r;
}

// ---------------- host orchestration ----------------
extern "C" void kernel_launch(void* const* d_in, const int* in_sizes, int n_in,
                              void* d_out, int out_size) {
    (void)in_sizes; (void)n_in; (void)out_size;
    const float* hidden   = (const float*)d_in[0];
    const int*   pos      = (const int*)d_in[1];
    const float* ln1_w    = (const float*)d_in[2];
    const float* ln2_w    = (const float*)d_in[3];
    const float* q_w      = (const float*)d_in[4];
    const float* k_w      = (const float*)d_in[5];
    const float* v_w      = (const float*)d_in[6];
    const float* o_w      = (const float*)d_in[7];
    const float* router_w = (const float*)d_in[8];
    const float* r_bias   = (const float*)d_in[9];
    const float* eg_w     = (const float*)d_in[10];
    const float* eu_w     = (const float*)d_in[11];
    const float* ed_w     = (const float*)d_in[12];
    const float* sg_w     = (const float*)d_in[13];
    const float* su_w     = (const float*)d_in[14];
    const float* sd_w     = (const float*)d_in[15];
    float* out = (float*)d_out;

    float *h1, *qkv, *attn, *ao, *h2, *xb, *logits, *topkw, *egu, *act, *ed, *sgu, *act2, *sh;
    int *cnt, *list;
    cudaGetSymbolAddress((void**)&h1, g_h1);
    cudaGetSymbolAddress((void**)&qkv, g_qkv);
    cudaGetSymbolAddress((void**)&attn, g_attn);
    cudaGetSymbolAddress((void**)&ao, g_ao);
    cudaGetSymbolAddress((void**)&h2, g_h2);
    cudaGetSymbolAddress((void**)&xb, g_x);
    cudaGetSymbolAddress((void**)&logits, g_logits);
    cudaGetSymbolAddress((void**)&topkw, g_topkw);
    cudaGetSymbolAddress((void**)&cnt, g_cnt);
    cudaGetSymbolAddress((void**)&list, g_list);
    cudaGetSymbolAddress((void**)&egu, g_egu);
    cudaGetSymbolAddress((void**)&act, g_act);
    cudaGetSymbolAddress((void**)&ed, g_ed);
    cudaGetSymbolAddress((void**)&sgu, g_sgu);
    cudaGetSymbolAddress((void**)&act2, g_act2);
    cudaGetSymbolAddress((void**)&sh, g_sh);

    zero_cnt_kernel<<<1, 32>>>(cnt);

    // ----- attention branch -----
    rmsnorm_kernel<<<T, 256>>>(hidden, ln1_w, h1);
    {   // fused QKV: N = 2048 (q 0-1023 | k 1024-1535 | v 1536-2047), NT
        BSegs b = {{q_w, q_w, k_w, v_w}, {0, 0, 1024, 1536}, 1024, 0};
        gemm_bf16<true, false><<<dim3(16, 8), 256>>>(h1, 1024, b, qkv, 2048, T, 2048, H,
                                                     nullptr, nullptr, 0);
    }
    rope_kernel<<<T, dim3(64, 12)>>>(qkv, pos);
    attn_kernel<<<dim3(NH, T / 32), 256>>>(qkv, attn);
    {   // O projection, NT
        BSegs b = {{o_w, o_w, o_w, o_w}, {0, 0, 0, 0}, 1024, 0};
        gemm_bf16<true, false><<<dim3(8, 8), 256>>>(attn, 1024, b, ao, 1024, T, H, H,
                                                    nullptr, nullptr, 0);
    }
    add_kernel<<<(T * H + 255) / 256, 256>>>(hidden, ao, h2, T * H);

    // ----- MoE branch -----
    rmsnorm_kernel<<<T, 256>>>(h2, ln2_w, xb);
    gemm_f32_nt<<<dim3(1, T / 64), 256>>>(xb, router_w, logits, T, NE, H);
    router_kernel<<<(T + 255) / 256, 256>>>(logits, r_bias, topkw, cnt, list);

    {   // routed experts: gather GEMM, fused eg|eu (N=1024, ldb=512 each, NN)
        BSegs b = {{eg_w, eu_w, eg_w, eu_w}, {0, 512, 0, 512}, 512, (size_t)H * MI};
        gemm_bf16<false, true><<<dim3(8, 8, NE), 256>>>(xb, 1024, b, egu, 1024, T * 4, 1024, H,
                                                        cnt, list, 2);
    }
    silu_pair_kernel<<<(T * 4 * 512 + 255) / 256, 256>>>(egu, act, T * 4 * 512, 512, 1024);
    {   // expert down: gather GEMM, NN
        BSegs b = {{ed_w, ed_w, ed_w, ed_w}, {0, 0, 0, 0}, 1024, (size_t)MI * H};
        gemm_bf16<false, true><<<dim3(8, 8, NE), 256>>>(act, 512, b, ed, 1024, T * 4, 1024, MI,
                                                        cnt, list, 0);
    }

    {   // shared expert: fused sg|su (N=2048, NN)
        BSegs b = {{sg_w, sg_w, su_w, su_w}, {0, 0, 1024, 1024}, 1024, 0};
        gemm_bf16<false, false><<<dim3(16, 8), 256>>>(xb, 1024, b, sgu, 2048, T, 2048, H,
                                                      nullptr, nullptr, 0);
    }
    silu_pair_kernel<<<(T * SI + 255) / 256, 256>>>(sgu, act2, T * SI, 1024, 2048);
    {   // shared down, NN
        BSegs b = {{sd_w, sd_w, sd_w, sd_w}, {0, 0, 0, 0}, 1024, 0};
        gemm_bf16<false, false><<<dim3(8, 8), 256>>>(act2, 1024, b, sh, 1024, T, H, SI,
                                                     nullptr, nullptr, 0);
    }

    final_kernel<<<(T * H + 255) / 256, 256>>>(h2, sh, ed, topkw, out);
}